// round 10
// baseline (speedup 1.0000x reference)
#include <cuda_runtime.h>
#include <cuda_fp16.h>
#include <cstdint>

#define LL 32768
#define HH 256
#define NS 512
#define CT 128
#define NC 256

// ---------------- device scratch ---------------------------------------------
__device__ __half g_bur[(size_t)LL * NS];      // Bu real fp16
__device__ __half g_bui[(size_t)LL * NS];      // Bu imag fp16
__device__ __half g_sh[(size_t)LL * 2 * NS];   // states fp16 [L][1024] (re|im)
__device__ __half g_uh[(size_t)LL * HH];       // U fp16
__device__ __half g_bchi[2 * NS * HH];         // reordered gamma-B hi
__device__ __half g_bclo[2 * NS * HH];         // reordered gamma-B lo
__device__ __half g_cchi[HH * 2 * NS];         // [256][1024]: Cre | -Cim hi
__device__ __half g_cclo[HH * 2 * NS];
__device__ float2 g_chunk[NC * NS];
__device__ float2 g_pref[NC * NS];
__device__ float2 g_lam[NS];
__device__ float2 g_lamT[NS];
__device__ float  g_gamma[NS];

// ---------------- helpers ----------------------------------------------------
__device__ __forceinline__ float2 cmul(float2 a, float2 b) {
    return make_float2(a.x * b.x - a.y * b.y, a.x * b.y + a.y * b.x);
}
__device__ __forceinline__ void h16_split(float x, __half& hi, __half& lo) {
    hi = __float2half_rn(x);
    lo = __float2half_rn(x - __half2float(hi));
}
__device__ __forceinline__ uint32_t smem_u32(const void* p) {
    return (uint32_t)__cvta_generic_to_shared(p);
}
__device__ __forceinline__ void cpa16(const void* dst_smem, const void* src) {
    asm volatile("cp.async.cg.shared.global [%0], [%1], 16;"
                 :: "r"(smem_u32(dst_smem)), "l"(src));
}
#define CPA_COMMIT asm volatile("cp.async.commit_group;")

__device__ __forceinline__ void mma16(float* c, const uint32_t* a, const uint32_t* b) {
    asm volatile(
        "mma.sync.aligned.m16n8k16.row.col.f32.f16.f16.f32 "
        "{%0,%1,%2,%3},{%4,%5,%6,%7},{%8,%9},{%0,%1,%2,%3};"
        : "+f"(c[0]), "+f"(c[1]), "+f"(c[2]), "+f"(c[3])
        : "r"(a[0]), "r"(a[1]), "r"(a[2]), "r"(a[3]), "r"(b[0]), "r"(b[1]));
}
__device__ __forceinline__ void ldm_x4(uint32_t* r, uint32_t addr) {
    asm volatile("ldmatrix.sync.aligned.m8n8.x4.shared.b16 {%0,%1,%2,%3}, [%4];"
                 : "=r"(r[0]), "=r"(r[1]), "=r"(r[2]), "=r"(r[3]) : "r"(addr));
}

// ---------------- setup kernels ----------------------------------------------
__global__ void k_setup(const float* __restrict__ nu_log,
                        const float* __restrict__ theta_log) {
    int n = threadIdx.x;
    if (n >= NS) return;
    float nu    = expf(nu_log[n]);
    float theta = expf(theta_log[n]);
    float mag   = expf(-nu);
    float2 lam  = make_float2(mag * cosf(theta), mag * sinf(theta));
    g_lam[n]   = lam;
    g_gamma[n] = sqrtf(fmaxf(1.0f - mag * mag, 0.0f));
    float2 t = lam;
    #pragma unroll
    for (int i = 0; i < 7; i++) t = cmul(t, t);
    g_lamT[n] = t;
}

__global__ void k_cvtU(const float* __restrict__ U) {
    size_t i = ((size_t)blockIdx.x * 256 + threadIdx.x) * 4;
    if (i >= (size_t)LL * HH) return;
    float4 v = *(const float4*)&U[i];
    *(__half2*)&g_uh[i]     = __halves2half2(__float2half_rn(v.x), __float2half_rn(v.y));
    *(__half2*)&g_uh[i + 2] = __halves2half2(__float2half_rn(v.z), __float2half_rn(v.w));
}

// bcat layout: group g = n/32 owns rows [64g, 64g+64): first 32 = re, next 32 = im
__global__ void k_bn(const float* __restrict__ Bre, const float* __restrict__ Bim) {
    int i = blockIdx.x * 256 + threadIdx.x;
    if (i >= NS * HH) return;
    int n = i / HH, h = i % HH;
    float gam = g_gamma[n];
    int grp = n >> 5, j = n & 31;
    size_t rr = (size_t)(grp * 64 + j) * HH + h;
    size_t ri = (size_t)(grp * 64 + 32 + j) * HH + h;
    __half hi, lo;
    h16_split(Bre[i] * gam, hi, lo);  g_bchi[rr] = hi;  g_bclo[rr] = lo;
    h16_split(Bim[i] * gam, hi, lo);  g_bchi[ri] = hi;  g_bclo[ri] = lo;
}

__global__ void k_cc(const float* __restrict__ Cre, const float* __restrict__ Cim) {
    int i = blockIdx.x * 256 + threadIdx.x;
    if (i >= HH * NS) return;
    int h = i / NS, n = i % NS;
    __half hi, lo;
    h16_split(Cre[i], hi, lo);
    g_cchi[(size_t)h * (2*NS) + n] = hi;  g_cclo[(size_t)h * (2*NS) + n] = lo;
    h16_split(-Cim[i], hi, lo);
    g_cchi[(size_t)h * (2*NS) + NS + n] = hi;  g_cclo[(size_t)h * (2*NS) + NS + n] = lo;
}

// ---------------- GEMM machinery ---------------------------------------------
// Block 256(M) x 64(N) x 32(K); 256 thr = 8 warps (4M x 2N); warp tile 64x32.
// B kept hi+lo (2-pass). Rows 40 halfs (80B). 3-stage ring, 1 sync/stage.
static constexpr int ROWB    = 80;
static constexpr int A_BYTES = 256 * ROWB;             // 20480
static constexpr int B_BYTES = 64 * ROWB;              // 5120
static constexpr int STG_B   = A_BYTES + 2 * B_BYTES;  // 30720
static constexpr int SMEM_DYN = 3 * STG_B;             // 92160

__device__ __forceinline__ void load_stage(char* stg, const __half* gA, int lda,
                                           const __half* gBh, const __half* gBl,
                                           int ldb, int k0, int t) {
    __half* A  = (__half*)stg;
    __half* Bh = (__half*)(stg + A_BYTES);
    __half* Bl = (__half*)(stg + A_BYTES + B_BYTES);
    #pragma unroll
    for (int i = 0; i < 4; i++) {            // A: 256 rows x 4 chunks of 16B
        int idx = t + i * 256;
        int r = idx >> 2, c = idx & 3;
        cpa16(&A[r * 40 + c * 8], gA + (size_t)r * lda + k0 + c * 8);
    }
    {
        int r = t >> 2, c = t & 3;           // B: 64 rows x 4 chunks, hi + lo
        cpa16(&Bh[r * 40 + c * 8], gBh + (size_t)r * ldb + k0 + c * 8);
        cpa16(&Bl[r * 40 + c * 8], gBl + (size_t)r * ldb + k0 + c * 8);
    }
}

__device__ __forceinline__ void mk_offsets(int wm, int wn, int lane,
                                           uint32_t* oA, uint32_t* oB) {
    #pragma unroll
    for (int mi = 0; mi < 4; mi++) {
        int row = wm * 64 + mi * 16 + (lane & 15);
        oA[mi] = (uint32_t)(row * ROWB + (8 * (lane >> 4)) * 2);
    }
    #pragma unroll
    for (int p = 0; p < 2; p++) {
        int row = wn * 32 + p * 16 + ((lane >> 4) << 3) + (lane & 7);
        oB[p] = (uint32_t)(A_BYTES + row * ROWB + (8 * ((lane >> 3) & 1)) * 2);
    }
}

__device__ __forceinline__ void compute_stage(uint32_t sb,
                                              const uint32_t* oA, const uint32_t* oB,
                                              float acc[4][4][4]) {
    #pragma unroll
    for (int kk = 0; kk < 2; kk++) {
        uint32_t af[4][4], bh[2][4], bl[2][4];
        #pragma unroll
        for (int mi = 0; mi < 4; mi++) ldm_x4(af[mi], sb + oA[mi] + kk * 32);
        ldm_x4(bh[0], sb + oB[0] + kk * 32);
        ldm_x4(bh[1], sb + oB[1] + kk * 32);
        ldm_x4(bl[0], sb + oB[0] + B_BYTES + kk * 32);
        ldm_x4(bl[1], sb + oB[1] + B_BYTES + kk * 32);
        #pragma unroll
        for (int mi = 0; mi < 4; mi++)
            #pragma unroll
            for (int p = 0; p < 2; p++) {
                mma16(acc[mi][2*p],     af[mi], &bh[p][0]);
                mma16(acc[mi][2*p + 1], af[mi], &bh[p][2]);
                mma16(acc[mi][2*p],     af[mi], &bl[p][0]);
                mma16(acc[mi][2*p + 1], af[mi], &bl[p][2]);
            }
    }
}

// ring loop shared by both GEMMs (3-stage, 1 sync per 32-K stage)
#define GEMM_RING(KT, GA, LDA_, GBH, GBL)                                        \
    load_stage(dynsm, GA, LDA_, GBH, GBL, LDA_, 0, t);  CPA_COMMIT;              \
    load_stage(dynsm + STG_B, GA, LDA_, GBH, GBL, LDA_, 32, t); CPA_COMMIT;      \
    for (int it = 0; it < (KT); it++) {                                          \
        if (it + 1 < (KT)) { asm volatile("cp.async.wait_group 1;"); }           \
        else               { asm volatile("cp.async.wait_group 0;"); }           \
        __syncthreads();                                                         \
        if (it + 2 < (KT)) {                                                     \
            load_stage(dynsm + ((it + 2) % 3) * STG_B, GA, LDA_, GBH, GBL,       \
                       LDA_, (it + 2) * 32, t);                                  \
            CPA_COMMIT;                                                          \
        }                                                                        \
        compute_stage(sb0 + ((it) % 3) * STG_B, oA, oB, acc);                    \
    }

// ---------------- GEMM1 + fused chunk reduce ---------------------------------
// grid (16, 128): x = state-group (32 n's, 64 bcat rows), y = 256 L-rows = 2 chunks
__global__ __launch_bounds__(256) void k_gemm1() {
    extern __shared__ char dynsm[];
    __shared__ float2 seg[4][32];
    int t = threadIdx.x;
    int w = t >> 5, lane = t & 31, g = lane >> 2, t4 = lane & 3;
    int wm = w >> 1, wn = w & 1;
    int row0 = blockIdx.y * 256;
    int n0 = blockIdx.x * 32;
    uint32_t sb0 = smem_u32(dynsm);

    uint32_t oA[4], oB[2];
    mk_offsets(wm, wn, lane, oA, oB);

    const __half* gA  = g_uh   + (size_t)row0 * HH;
    const __half* gBh = g_bchi + (size_t)(blockIdx.x * 64) * HH;
    const __half* gBl = g_bclo + (size_t)(blockIdx.x * 64) * HH;

    float acc[4][4][4] = {};
    GEMM_RING(HH / 32, gA, HH, gBh, gBl);

    // Two 128-row halves; each half = one scan chunk.
    float (*ep)[68] = (float(*)[68])dynsm;
    #pragma unroll 1
    for (int half = 0; half < 2; half++) {
        __syncthreads();                    // ep free (ring dead / prev half done)
        if ((wm >> 1) == half) {
            int wmh = wm & 1;               // 0..1 within the half
            #pragma unroll
            for (int mi = 0; mi < 4; mi++) {
                int r0 = wmh * 64 + mi * 16 + g;
                #pragma unroll
                for (int ni = 0; ni < 4; ni++) {
                    int c = wn * 32 + ni * 8 + 2 * t4;
                    *(float2*)&ep[r0][c] =
                        make_float2(acc[mi][ni][0], acc[mi][ni][1]);
                    *(float2*)&ep[r0 + 8][c] =
                        make_float2(acc[mi][ni][2], acc[mi][ni][3]);
                }
            }
        }
        __syncthreads();

        // coalesced fp16 write of Bu for this half
        int hrow0 = row0 + half * 128;
        #pragma unroll
        for (int i = 0; i < 16; i++) {
            int fi = t + i * 256;
            int r = fi >> 5, p = fi & 31;
            if (p < 16) {
                __half2 v = __halves2half2(__float2half_rn(ep[r][2*p]),
                                           __float2half_rn(ep[r][2*p + 1]));
                *(__half2*)&g_bur[(size_t)(hrow0 + r) * NS + n0 + 2*p] = v;
            } else {
                int q = p - 16;
                __half2 v = __halves2half2(__float2half_rn(ep[r][32 + 2*q]),
                                           __float2half_rn(ep[r][32 + 2*q + 1]));
                *(__half2*)&g_bui[(size_t)(hrow0 + r) * NS + n0 + 2*q] = v;
            }
        }

        // fused chunk Horner: 4 warps x 32-row segments + lambda^32 combine
        if (w < 4) {
            float2 lam = g_lam[n0 + lane];
            float2 b = make_float2(0.f, 0.f);
            int rbase = w * 32;
            #pragma unroll 4
            for (int r = 0; r < 32; r++) {
                float2 tt = cmul(lam, b);
                b = make_float2(tt.x + ep[rbase + r][lane],
                                tt.y + ep[rbase + r][32 + lane]);
            }
            seg[w][lane] = b;
        }
        __syncthreads();
        if (w == 0) {
            float2 lam = g_lam[n0 + lane];
            float2 l32 = lam;
            #pragma unroll
            for (int i = 0; i < 5; i++) l32 = cmul(l32, l32);
            float2 b = seg[0][lane];
            #pragma unroll
            for (int s = 1; s < 4; s++) {
                float2 tt = cmul(l32, b);
                b = make_float2(tt.x + seg[s][lane].x, tt.y + seg[s][lane].y);
            }
            g_chunk[(blockIdx.y * 2 + half) * NS + n0 + lane] = b;
        }
    }
}

// ---------------- cross-chunk scan -------------------------------------------
__global__ __launch_bounds__(512) void k_scan() {
    int n = threadIdx.x;
    float2 lamT = g_lamT[n];
    float2 p = make_float2(0.f, 0.f);
    for (int c = 0; c < NC; c++) {
        g_pref[c * NS + n] = p;
        float2 b = g_chunk[c * NS + n];
        float2 tt = cmul(lamT, p);
        p = make_float2(tt.x + b.x, tt.y + b.y);
    }
}

// ---------------- apply: Bu fp16 -> states fp16 [L][1024] --------------------
__global__ __launch_bounds__(512) void k_apply() {
    int c = blockIdx.x;
    int n = threadIdx.x;
    float2 lam = g_lam[n];
    float2 carry = g_pref[c * NS + n];
    size_t base = (size_t)c * CT * NS + n;
    #pragma unroll 2
    for (int j = 0; j < CT; j++) {
        size_t idx = base + (size_t)j * NS;
        float vr = __half2float(g_bur[idx]);
        float vi = __half2float(g_bui[idx]);
        float2 tt = cmul(lam, carry);
        carry = make_float2(tt.x + vr, tt.y + vi);
        size_t l = (size_t)c * CT + j;
        g_sh[l * (2*NS) + n]      = __float2half_rn(carry.x);
        g_sh[l * (2*NS) + NS + n] = __float2half_rn(carry.y);
    }
}

// ---------------- GEMM2: Y = S @ cc^T + D*U ----------------------------------
// grid (4, 128): x = h-tile(64), y = L-tile(256). K = 1024.
__global__ __launch_bounds__(256) void k_gemm2(const float* __restrict__ U,
                                               const float* __restrict__ Dg,
                                               float* __restrict__ Y) {
    extern __shared__ char dynsm[];
    int t = threadIdx.x;
    int w = t >> 5, lane = t & 31, g = lane >> 2, t4 = lane & 3;
    int wm = w >> 1, wn = w & 1;
    int row0 = blockIdx.y * 256;
    int col0 = blockIdx.x * 64;
    uint32_t sb0 = smem_u32(dynsm);

    uint32_t oA[4], oB[2];
    mk_offsets(wm, wn, lane, oA, oB);

    const int LDA = 2 * NS;
    const __half* gA  = g_sh   + (size_t)row0 * LDA;
    const __half* gBh = g_cchi + (size_t)col0 * LDA;
    const __half* gBl = g_cclo + (size_t)col0 * LDA;

    float acc[4][4][4] = {};
    GEMM_RING((2 * NS) / 32, gA, LDA, gBh, gBl);

    #pragma unroll
    for (int mi = 0; mi < 4; mi++) {
        int l0 = row0 + wm * 64 + mi * 16 + g;
        #pragma unroll
        for (int ni = 0; ni < 4; ni++) {
            int h = col0 + wn * 32 + ni * 8 + 2 * t4;
            float2 d2 = *(const float2*)&Dg[h];
            float2 u0 = *(const float2*)&U[(size_t)l0 * HH + h];
            float2 u1 = *(const float2*)&U[(size_t)(l0 + 8) * HH + h];
            *(float2*)&Y[(size_t)l0 * HH + h] =
                make_float2(acc[mi][ni][0] + d2.x * u0.x, acc[mi][ni][1] + d2.y * u0.y);
            *(float2*)&Y[(size_t)(l0 + 8) * HH + h] =
                make_float2(acc[mi][ni][2] + d2.x * u1.x, acc[mi][ni][3] + d2.y * u1.y);
        }
    }
}

// ---------------- launch ----------------------------------------------------
extern "C" void kernel_launch(void* const* d_in, const int* in_sizes, int n_in,
                              void* d_out, int out_size) {
    const float* U        = (const float*)d_in[0];
    const float* nu_log   = (const float*)d_in[1];
    const float* theta_lg = (const float*)d_in[2];
    const float* Bre      = (const float*)d_in[3];
    const float* Bim      = (const float*)d_in[4];
    const float* Cre      = (const float*)d_in[5];
    const float* Cim      = (const float*)d_in[6];
    const float* D        = (const float*)d_in[7];
    float* Y = (float*)d_out;

    cudaFuncSetAttribute(k_gemm1, cudaFuncAttributeMaxDynamicSharedMemorySize, SMEM_DYN);
    cudaFuncSetAttribute(k_gemm2, cudaFuncAttributeMaxDynamicSharedMemorySize, SMEM_DYN);

    // order keeps k_gemm1 at launch slot 4 (where ncu lands)
    k_setup<<<1, 512>>>(nu_log, theta_lg);
    k_cvtU<<<(LL * HH / 4 + 255) / 256, 256>>>(U);
    k_bn<<<(NS * HH + 255) / 256, 256>>>(Bre, Bim);
    k_gemm1<<<dim3(16, 128), 256, SMEM_DYN>>>();
    k_cc<<<(HH * NS + 255) / 256, 256>>>(Cre, Cim);
    k_scan<<<1, 512>>>();
    k_apply<<<NC, 512>>>();
    k_gemm2<<<dim3(4, 128), 256, SMEM_DYN>>>(U, D, Y);
}

// round 11
// speedup vs baseline: 1.3546x; 1.3546x over previous
#include <cuda_runtime.h>
#include <cuda_fp16.h>
#include <cstdint>

#define LL 32768
#define HH 256
#define NS 512
#define CT 128
#define NC 256

// ---------------- device scratch ---------------------------------------------
__device__ __half g_bur[(size_t)LL * NS];      // Bu real fp16
__device__ __half g_bui[(size_t)LL * NS];      // Bu imag fp16
__device__ __half g_sh[(size_t)LL * 2 * NS];   // states fp16 [L][1024] (re|im)
__device__ __half g_uh[(size_t)LL * HH];       // U fp16
__device__ __half g_bchi[2 * NS * HH];         // reordered gamma-B hi
__device__ __half g_bclo[2 * NS * HH];         // reordered gamma-B lo
__device__ __half g_cchi[HH * 2 * NS];         // [256][1024]: Cre | -Cim hi
__device__ __half g_cclo[HH * 2 * NS];
__device__ float2 g_chunk[NC * NS];
__device__ float2 g_seg[16 * NS];              // per-segment Horner sums
__device__ float2 g_segpref[16 * NS];          // per-segment carry-in
__device__ float2 g_lam[NS];
__device__ float2 g_lamT[NS];
__device__ float  g_gamma[NS];

// ---------------- helpers ----------------------------------------------------
__device__ __forceinline__ float2 cmul(float2 a, float2 b) {
    return make_float2(a.x * b.x - a.y * b.y, a.x * b.y + a.y * b.x);
}
__device__ __forceinline__ void h16_split(float x, __half& hi, __half& lo) {
    hi = __float2half_rn(x);
    lo = __float2half_rn(x - __half2float(hi));
}
__device__ __forceinline__ uint32_t smem_u32(const void* p) {
    return (uint32_t)__cvta_generic_to_shared(p);
}
__device__ __forceinline__ void cpa16(const void* dst_smem, const void* src) {
    asm volatile("cp.async.cg.shared.global [%0], [%1], 16;"
                 :: "r"(smem_u32(dst_smem)), "l"(src));
}
#define CPA_COMMIT asm volatile("cp.async.commit_group;")

__device__ __forceinline__ void mma16(float* c, const uint32_t* a, const uint32_t* b) {
    asm volatile(
        "mma.sync.aligned.m16n8k16.row.col.f32.f16.f16.f32 "
        "{%0,%1,%2,%3},{%4,%5,%6,%7},{%8,%9},{%0,%1,%2,%3};"
        : "+f"(c[0]), "+f"(c[1]), "+f"(c[2]), "+f"(c[3])
        : "r"(a[0]), "r"(a[1]), "r"(a[2]), "r"(a[3]), "r"(b[0]), "r"(b[1]));
}
__device__ __forceinline__ void ldm_x4(uint32_t* r, uint32_t addr) {
    asm volatile("ldmatrix.sync.aligned.m8n8.x4.shared.b16 {%0,%1,%2,%3}, [%4];"
                 : "=r"(r[0]), "=r"(r[1]), "=r"(r[2]), "=r"(r[3]) : "r"(addr));
}

// ---------------- setup kernels ----------------------------------------------
__global__ void k_setup(const float* __restrict__ nu_log,
                        const float* __restrict__ theta_log) {
    int n = threadIdx.x;
    if (n >= NS) return;
    float nu    = expf(nu_log[n]);
    float theta = expf(theta_log[n]);
    float mag   = expf(-nu);
    float2 lam  = make_float2(mag * cosf(theta), mag * sinf(theta));
    g_lam[n]   = lam;
    g_gamma[n] = sqrtf(fmaxf(1.0f - mag * mag, 0.0f));
    float2 t = lam;
    #pragma unroll
    for (int i = 0; i < 7; i++) t = cmul(t, t);
    g_lamT[n] = t;
}

__global__ void k_cvtU(const float* __restrict__ U) {
    size_t i = ((size_t)blockIdx.x * 256 + threadIdx.x) * 4;
    if (i >= (size_t)LL * HH) return;
    float4 v = *(const float4*)&U[i];
    *(__half2*)&g_uh[i]     = __halves2half2(__float2half_rn(v.x), __float2half_rn(v.y));
    *(__half2*)&g_uh[i + 2] = __halves2half2(__float2half_rn(v.z), __float2half_rn(v.w));
}

// bcat layout: group g = n/32 owns rows [64g, 64g+64): first 32 = re, next 32 = im
__global__ void k_bn(const float* __restrict__ Bre, const float* __restrict__ Bim) {
    int i = blockIdx.x * 256 + threadIdx.x;
    if (i >= NS * HH) return;
    int n = i / HH, h = i % HH;
    float gam = g_gamma[n];
    int grp = n >> 5, j = n & 31;
    size_t rr = (size_t)(grp * 64 + j) * HH + h;
    size_t ri = (size_t)(grp * 64 + 32 + j) * HH + h;
    __half hi, lo;
    h16_split(Bre[i] * gam, hi, lo);  g_bchi[rr] = hi;  g_bclo[rr] = lo;
    h16_split(Bim[i] * gam, hi, lo);  g_bchi[ri] = hi;  g_bclo[ri] = lo;
}

__global__ void k_cc(const float* __restrict__ Cre, const float* __restrict__ Cim) {
    int i = blockIdx.x * 256 + threadIdx.x;
    if (i >= HH * NS) return;
    int h = i / NS, n = i % NS;
    __half hi, lo;
    h16_split(Cre[i], hi, lo);
    g_cchi[(size_t)h * (2*NS) + n] = hi;  g_cclo[(size_t)h * (2*NS) + n] = lo;
    h16_split(-Cim[i], hi, lo);
    g_cchi[(size_t)h * (2*NS) + NS + n] = hi;  g_cclo[(size_t)h * (2*NS) + NS + n] = lo;
}

// ---------------- GEMM machinery (round-9 config) -----------------------------
// Block 128(M) x 64(N) x 32(K); 256 thr = 8 warps (4M x 2N); warp 32x32.
// B kept as hi+lo (2-pass). Rows 40 halfs (80B). 3-stage ring, 1 sync/stage.
static constexpr int ROWB    = 80;
static constexpr int A_BYTES = 128 * ROWB;             // 10240
static constexpr int B_BYTES = 64 * ROWB;              // 5120
static constexpr int STG_B   = A_BYTES + 2 * B_BYTES;  // 20480
static constexpr int SMEM_DYN = 3 * STG_B;             // 61440

__device__ __forceinline__ void load_stage(char* stg, const __half* gA, int lda,
                                           const __half* gBh, const __half* gBl,
                                           int ldb, int k0, int t) {
    __half* A  = (__half*)stg;
    __half* Bh = (__half*)(stg + A_BYTES);
    __half* Bl = (__half*)(stg + A_BYTES + B_BYTES);
    #pragma unroll
    for (int i = 0; i < 2; i++) {
        int idx = t + i * 256;
        int r = idx >> 2, c = idx & 3;
        cpa16(&A[r * 40 + c * 8], gA + (size_t)r * lda + k0 + c * 8);
    }
    {
        int r = t >> 2, c = t & 3;
        cpa16(&Bh[r * 40 + c * 8], gBh + (size_t)r * ldb + k0 + c * 8);
        cpa16(&Bl[r * 40 + c * 8], gBl + (size_t)r * ldb + k0 + c * 8);
    }
}

__device__ __forceinline__ void mk_offsets(int wm, int wn, int lane,
                                           uint32_t* oA, uint32_t* oB) {
    #pragma unroll
    for (int mi = 0; mi < 2; mi++) {
        int row = wm * 32 + mi * 16 + (lane & 15);
        oA[mi] = (uint32_t)(row * ROWB + (8 * (lane >> 4)) * 2);
    }
    #pragma unroll
    for (int p = 0; p < 2; p++) {
        int row = wn * 32 + p * 16 + ((lane >> 4) << 3) + (lane & 7);
        oB[p] = (uint32_t)(A_BYTES + row * ROWB + (8 * ((lane >> 3) & 1)) * 2);
    }
}

__device__ __forceinline__ void compute_stage(uint32_t sb,
                                              const uint32_t* oA, const uint32_t* oB,
                                              float acc[2][4][4]) {
    #pragma unroll
    for (int kk = 0; kk < 2; kk++) {
        uint32_t af[2][4], bh[2][4], bl[2][4];
        ldm_x4(af[0], sb + oA[0] + kk * 32);
        ldm_x4(af[1], sb + oA[1] + kk * 32);
        ldm_x4(bh[0], sb + oB[0] + kk * 32);
        ldm_x4(bh[1], sb + oB[1] + kk * 32);
        ldm_x4(bl[0], sb + oB[0] + B_BYTES + kk * 32);
        ldm_x4(bl[1], sb + oB[1] + B_BYTES + kk * 32);
        #pragma unroll
        for (int mi = 0; mi < 2; mi++)
            #pragma unroll
            for (int p = 0; p < 2; p++) {
                mma16(acc[mi][2*p],     af[mi], &bh[p][0]);
                mma16(acc[mi][2*p + 1], af[mi], &bh[p][2]);
                mma16(acc[mi][2*p],     af[mi], &bl[p][0]);
                mma16(acc[mi][2*p + 1], af[mi], &bl[p][2]);
            }
    }
}

#define GEMM_RING(KT, GA, LDA_, GBH, GBL)                                        \
    load_stage(dynsm, GA, LDA_, GBH, GBL, LDA_, 0, t);  CPA_COMMIT;              \
    load_stage(dynsm + STG_B, GA, LDA_, GBH, GBL, LDA_, 32, t); CPA_COMMIT;      \
    for (int it = 0; it < (KT); it++) {                                          \
        if (it + 1 < (KT)) { asm volatile("cp.async.wait_group 1;"); }           \
        else               { asm volatile("cp.async.wait_group 0;"); }           \
        __syncthreads();                                                         \
        if (it + 2 < (KT)) {                                                     \
            load_stage(dynsm + ((it + 2) % 3) * STG_B, GA, LDA_, GBH, GBL,       \
                       LDA_, (it + 2) * 32, t);                                  \
            CPA_COMMIT;                                                          \
        }                                                                        \
        compute_stage(sb0 + ((it) % 3) * STG_B, oA, oB, acc);                    \
    }

// ---------------- GEMM1 + fused chunk reduce ---------------------------------
// grid (16, 256): x = state-group (32 n's, 64 bcat rows), y = chunk (128 L-rows)
__global__ __launch_bounds__(256) void k_gemm1() {
    extern __shared__ char dynsm[];
    __shared__ float2 seg[4][32];
    int t = threadIdx.x;
    int w = t >> 5, lane = t & 31, g = lane >> 2, t4 = lane & 3;
    int wm = w >> 1, wn = w & 1;
    int row0 = blockIdx.y * 128;
    int n0 = blockIdx.x * 32;
    uint32_t sb0 = smem_u32(dynsm);

    uint32_t oA[2], oB[2];
    mk_offsets(wm, wn, lane, oA, oB);

    const __half* gA  = g_uh   + (size_t)row0 * HH;
    const __half* gBh = g_bchi + (size_t)(blockIdx.x * 64) * HH;
    const __half* gBl = g_bclo + (size_t)(blockIdx.x * 64) * HH;

    float acc[2][4][4] = {};
    GEMM_RING(HH / 32, gA, HH, gBh, gBl);
    __syncthreads();

    float (*ep)[68] = (float(*)[68])dynsm;
    #pragma unroll
    for (int mi = 0; mi < 2; mi++) {
        int r0 = wm * 32 + mi * 16 + g;
        #pragma unroll
        for (int ni = 0; ni < 4; ni++) {
            int c = wn * 32 + ni * 8 + 2 * t4;
            *(float2*)&ep[r0][c]     = make_float2(acc[mi][ni][0], acc[mi][ni][1]);
            *(float2*)&ep[r0 + 8][c] = make_float2(acc[mi][ni][2], acc[mi][ni][3]);
        }
    }
    __syncthreads();

    // coalesced fp16 write of Bu
    #pragma unroll
    for (int i = 0; i < 16; i++) {
        int fi = t + i * 256;
        int r = fi >> 5, p = fi & 31;
        if (p < 16) {
            __half2 v = __halves2half2(__float2half_rn(ep[r][2*p]),
                                       __float2half_rn(ep[r][2*p + 1]));
            *(__half2*)&g_bur[(size_t)(row0 + r) * NS + n0 + 2*p] = v;
        } else {
            int q = p - 16;
            __half2 v = __halves2half2(__float2half_rn(ep[r][32 + 2*q]),
                                       __float2half_rn(ep[r][32 + 2*q + 1]));
            *(__half2*)&g_bui[(size_t)(row0 + r) * NS + n0 + 2*q] = v;
        }
    }

    // fused chunk Horner
    if (w < 4) {
        float2 lam = g_lam[n0 + lane];
        float2 b = make_float2(0.f, 0.f);
        int rbase = w * 32;
        #pragma unroll 4
        for (int r = 0; r < 32; r++) {
            float2 tt = cmul(lam, b);
            b = make_float2(tt.x + ep[rbase + r][lane],
                            tt.y + ep[rbase + r][32 + lane]);
        }
        seg[w][lane] = b;
    }
    __syncthreads();
    if (w == 0) {
        float2 lam = g_lam[n0 + lane];
        float2 l32 = lam;
        #pragma unroll
        for (int i = 0; i < 5; i++) l32 = cmul(l32, l32);
        float2 b = seg[0][lane];
        #pragma unroll
        for (int s = 1; s < 4; s++) {
            float2 tt = cmul(l32, b);
            b = make_float2(tt.x + seg[s][lane].x, tt.y + seg[s][lane].y);
        }
        g_chunk[blockIdx.y * NS + n0 + lane] = b;
    }
}

// ---------------- two-level cross-chunk scan ----------------------------------
// 256 chunks = 16 segments x 16 chunks.
// k_scan1 (16 blocks): segment Horner sums (loads batched for MLP)
__global__ __launch_bounds__(512) void k_scan1() {
    int s = blockIdx.x, n = threadIdx.x;
    float2 lamT = g_lamT[n];
    float2 v[16];
    #pragma unroll
    for (int j = 0; j < 16; j++) v[j] = g_chunk[(s * 16 + j) * NS + n];
    float2 b = make_float2(0.f, 0.f);
    #pragma unroll
    for (int j = 0; j < 16; j++) {
        float2 tt = cmul(lamT, b);
        b = make_float2(tt.x + v[j].x, tt.y + v[j].y);
    }
    g_seg[s * NS + n] = b;
}

// k_scan2 (1 block): prefix over 16 segments with multiplier lamT^16
__global__ __launch_bounds__(512) void k_scan2() {
    int n = threadIdx.x;
    float2 lamT = g_lamT[n];
    float2 l16 = lamT;
    #pragma unroll
    for (int i = 0; i < 4; i++) l16 = cmul(l16, l16);
    float2 v[16];
    #pragma unroll
    for (int s = 0; s < 16; s++) v[s] = g_seg[s * NS + n];
    float2 p = make_float2(0.f, 0.f);
    #pragma unroll
    for (int s = 0; s < 16; s++) {
        g_segpref[s * NS + n] = p;
        float2 tt = cmul(l16, p);
        p = make_float2(tt.x + v[s].x, tt.y + v[s].y);
    }
}

// ---------------- apply: segpref + intra-segment walk, batch-8 MLP ------------
__global__ __launch_bounds__(512) void k_apply() {
    int c = blockIdx.x;
    int n = threadIdx.x;
    int s = c >> 4, jrem = c & 15;
    float2 lam  = g_lam[n];
    float2 lamT = g_lamT[n];

    // chunk carry-in: segment prefix advanced over preceding chunks in segment
    float2 carry = g_segpref[s * NS + n];
    for (int j = 0; j < jrem; j++) {
        float2 b = g_chunk[(s * 16 + j) * NS + n];
        float2 tt = cmul(lamT, carry);
        carry = make_float2(tt.x + b.x, tt.y + b.y);
    }

    size_t base = (size_t)c * CT * NS + n;
    for (int j0 = 0; j0 < CT; j0 += 8) {
        float vr[8], vi[8];
        #pragma unroll
        for (int k = 0; k < 8; k++) {
            size_t idx = base + (size_t)(j0 + k) * NS;
            vr[k] = __half2float(g_bur[idx]);
            vi[k] = __half2float(g_bui[idx]);
        }
        #pragma unroll
        for (int k = 0; k < 8; k++) {
            float2 tt = cmul(lam, carry);
            carry = make_float2(tt.x + vr[k], tt.y + vi[k]);
            size_t l = (size_t)c * CT + j0 + k;
            g_sh[l * (2*NS) + n]      = __float2half_rn(carry.x);
            g_sh[l * (2*NS) + NS + n] = __float2half_rn(carry.y);
        }
    }
}

// ---------------- GEMM2: Y = S @ cc^T + D*U ----------------------------------
// grid (4, 256): x = h-tile(64), y = L-tile(128). K = 1024.
__global__ __launch_bounds__(256) void k_gemm2(const float* __restrict__ U,
                                               const float* __restrict__ Dg,
                                               float* __restrict__ Y) {
    extern __shared__ char dynsm[];
    int t = threadIdx.x;
    int w = t >> 5, lane = t & 31, g = lane >> 2, t4 = lane & 3;
    int wm = w >> 1, wn = w & 1;
    int row0 = blockIdx.y * 128;
    int col0 = blockIdx.x * 64;
    uint32_t sb0 = smem_u32(dynsm);

    uint32_t oA[2], oB[2];
    mk_offsets(wm, wn, lane, oA, oB);

    const int LDA = 2 * NS;
    const __half* gA  = g_sh   + (size_t)row0 * LDA;
    const __half* gBh = g_cchi + (size_t)col0 * LDA;
    const __half* gBl = g_cclo + (size_t)col0 * LDA;

    float acc[2][4][4] = {};
    GEMM_RING((2 * NS) / 32, gA, LDA, gBh, gBl);

    #pragma unroll
    for (int mi = 0; mi < 2; mi++) {
        int l0 = row0 + wm * 32 + mi * 16 + g;
        #pragma unroll
        for (int ni = 0; ni < 4; ni++) {
            int h = col0 + wn * 32 + ni * 8 + 2 * t4;
            float2 d2 = *(const float2*)&Dg[h];
            float2 u0 = *(const float2*)&U[(size_t)l0 * HH + h];
            float2 u1 = *(const float2*)&U[(size_t)(l0 + 8) * HH + h];
            *(float2*)&Y[(size_t)l0 * HH + h] =
                make_float2(acc[mi][ni][0] + d2.x * u0.x, acc[mi][ni][1] + d2.y * u0.y);
            *(float2*)&Y[(size_t)(l0 + 8) * HH + h] =
                make_float2(acc[mi][ni][2] + d2.x * u1.x, acc[mi][ni][3] + d2.y * u1.y);
        }
    }
}

// ---------------- launch ----------------------------------------------------
extern "C" void kernel_launch(void* const* d_in, const int* in_sizes, int n_in,
                              void* d_out, int out_size) {
    const float* U        = (const float*)d_in[0];
    const float* nu_log   = (const float*)d_in[1];
    const float* theta_lg = (const float*)d_in[2];
    const float* Bre      = (const float*)d_in[3];
    const float* Bim      = (const float*)d_in[4];
    const float* Cre      = (const float*)d_in[5];
    const float* Cim      = (const float*)d_in[6];
    const float* D        = (const float*)d_in[7];
    float* Y = (float*)d_out;

    cudaFuncSetAttribute(k_gemm1, cudaFuncAttributeMaxDynamicSharedMemorySize, SMEM_DYN);
    cudaFuncSetAttribute(k_gemm2, cudaFuncAttributeMaxDynamicSharedMemorySize, SMEM_DYN);

    // order keeps k_gemm1 at launch slot 4 (where ncu lands)
    k_setup<<<1, 512>>>(nu_log, theta_lg);
    k_cvtU<<<(LL * HH / 4 + 255) / 256, 256>>>(U);
    k_bn<<<(NS * HH + 255) / 256, 256>>>(Bre, Bim);
    k_gemm1<<<dim3(16, 256), 256, SMEM_DYN>>>();
    k_cc<<<(HH * NS + 255) / 256, 256>>>(Cre, Cim);
    k_scan1<<<16, 512>>>();
    k_scan2<<<1, 512>>>();
    k_apply<<<NC, 512>>>();
    k_gemm2<<<dim3(4, 256), 256, SMEM_DYN>>>(U, D, Y);
}

// round 12
// speedup vs baseline: 1.4283x; 1.0544x over previous
#include <cuda_runtime.h>
#include <cuda_fp16.h>
#include <cstdint>

#define LL 32768
#define HH 256
#define NS 512
#define CT 128
#define NC 256

// ---------------- device scratch ---------------------------------------------
__device__ __half g_bur[(size_t)LL * NS];      // Bu real fp16
__device__ __half g_bui[(size_t)LL * NS];      // Bu imag fp16
__device__ __half g_sh[(size_t)LL * 2 * NS];   // states fp16 [L][1024] (re|im)
__device__ __half g_uh[(size_t)LL * HH];       // U fp16
__device__ __half g_bchi[2 * NS * HH];         // reordered gamma-B hi
__device__ __half g_bclo[2 * NS * HH];         // reordered gamma-B lo
__device__ __half g_cchi[HH * 2 * NS];         // [256][1024]: Cre | -Cim hi
__device__ __half g_cclo[HH * 2 * NS];
__device__ float2 g_chunk[NC * NS];
__device__ float2 g_seg[16 * NS];              // per-segment Horner sums
__device__ float2 g_segpref[16 * NS];          // per-segment carry-in
__device__ float2 g_lam[NS];
__device__ float2 g_lamT[NS];
__device__ float  g_gamma[NS];

// ---------------- helpers ----------------------------------------------------
__device__ __forceinline__ float2 cmul(float2 a, float2 b) {
    return make_float2(a.x * b.x - a.y * b.y, a.x * b.y + a.y * b.x);
}
__device__ __forceinline__ void h16_split(float x, __half& hi, __half& lo) {
    hi = __float2half_rn(x);
    lo = __float2half_rn(x - __half2float(hi));
}
__device__ __forceinline__ uint32_t smem_u32(const void* p) {
    return (uint32_t)__cvta_generic_to_shared(p);
}
__device__ __forceinline__ void cpa16(const void* dst_smem, const void* src) {
    asm volatile("cp.async.cg.shared.global [%0], [%1], 16;"
                 :: "r"(smem_u32(dst_smem)), "l"(src));
}
#define CPA_COMMIT asm volatile("cp.async.commit_group;")

__device__ __forceinline__ void mma16(float* c, const uint32_t* a, const uint32_t* b) {
    asm volatile(
        "mma.sync.aligned.m16n8k16.row.col.f32.f16.f16.f32 "
        "{%0,%1,%2,%3},{%4,%5,%6,%7},{%8,%9},{%0,%1,%2,%3};"
        : "+f"(c[0]), "+f"(c[1]), "+f"(c[2]), "+f"(c[3])
        : "r"(a[0]), "r"(a[1]), "r"(a[2]), "r"(a[3]), "r"(b[0]), "r"(b[1]));
}
__device__ __forceinline__ void ldm_x4(uint32_t* r, uint32_t addr) {
    asm volatile("ldmatrix.sync.aligned.m8n8.x4.shared.b16 {%0,%1,%2,%3}, [%4];"
                 : "=r"(r[0]), "=r"(r[1]), "=r"(r[2]), "=r"(r[3]) : "r"(addr));
}

// ---------------- setup kernels ----------------------------------------------
__global__ void k_setup(const float* __restrict__ nu_log,
                        const float* __restrict__ theta_log) {
    int n = threadIdx.x;
    if (n >= NS) return;
    float nu    = expf(nu_log[n]);
    float theta = expf(theta_log[n]);
    float mag   = expf(-nu);
    float2 lam  = make_float2(mag * cosf(theta), mag * sinf(theta));
    g_lam[n]   = lam;
    g_gamma[n] = sqrtf(fmaxf(1.0f - mag * mag, 0.0f));
    float2 t = lam;
    #pragma unroll
    for (int i = 0; i < 7; i++) t = cmul(t, t);
    g_lamT[n] = t;
}

__global__ void k_cvtU(const float* __restrict__ U) {
    size_t i = ((size_t)blockIdx.x * 256 + threadIdx.x) * 4;
    if (i >= (size_t)LL * HH) return;
    float4 v = *(const float4*)&U[i];
    *(__half2*)&g_uh[i]     = __halves2half2(__float2half_rn(v.x), __float2half_rn(v.y));
    *(__half2*)&g_uh[i + 2] = __halves2half2(__float2half_rn(v.z), __float2half_rn(v.w));
}

// bcat layout: group g = n/32 owns rows [64g, 64g+64): first 32 = re, next 32 = im
__global__ void k_bn(const float* __restrict__ Bre, const float* __restrict__ Bim) {
    int i = blockIdx.x * 256 + threadIdx.x;
    if (i >= NS * HH) return;
    int n = i / HH, h = i % HH;
    float gam = g_gamma[n];
    int grp = n >> 5, j = n & 31;
    size_t rr = (size_t)(grp * 64 + j) * HH + h;
    size_t ri = (size_t)(grp * 64 + 32 + j) * HH + h;
    __half hi, lo;
    h16_split(Bre[i] * gam, hi, lo);  g_bchi[rr] = hi;  g_bclo[rr] = lo;
    h16_split(Bim[i] * gam, hi, lo);  g_bchi[ri] = hi;  g_bclo[ri] = lo;
}

__global__ void k_cc(const float* __restrict__ Cre, const float* __restrict__ Cim) {
    int i = blockIdx.x * 256 + threadIdx.x;
    if (i >= HH * NS) return;
    int h = i / NS, n = i % NS;
    __half hi, lo;
    h16_split(Cre[i], hi, lo);
    g_cchi[(size_t)h * (2*NS) + n] = hi;  g_cclo[(size_t)h * (2*NS) + n] = lo;
    h16_split(-Cim[i], hi, lo);
    g_cchi[(size_t)h * (2*NS) + NS + n] = hi;  g_cclo[(size_t)h * (2*NS) + NS + n] = lo;
}

// ---------------- GEMM machinery ---------------------------------------------
// Block 128(M) x 64(N) x 32(K); 256 thr = 8 warps (4M x 2N); warp 32x32.
// B hi+lo (2-pass). Rows 40 halfs (80B). 2-stage ring, 1 sync/stage,
// regs clamped for 4 CTAs/SM.
static constexpr int ROWB    = 80;
static constexpr int A_BYTES = 128 * ROWB;             // 10240
static constexpr int B_BYTES = 64 * ROWB;              // 5120
static constexpr int STG_B   = A_BYTES + 2 * B_BYTES;  // 20480
static constexpr int SMEM_DYN = 2 * STG_B;             // 40960

__device__ __forceinline__ void load_stage(char* stg, const __half* gA, int lda,
                                           const __half* gBh, const __half* gBl,
                                           int ldb, int k0, int t) {
    __half* A  = (__half*)stg;
    __half* Bh = (__half*)(stg + A_BYTES);
    __half* Bl = (__half*)(stg + A_BYTES + B_BYTES);
    #pragma unroll
    for (int i = 0; i < 2; i++) {
        int idx = t + i * 256;
        int r = idx >> 2, c = idx & 3;
        cpa16(&A[r * 40 + c * 8], gA + (size_t)r * lda + k0 + c * 8);
    }
    {
        int r = t >> 2, c = t & 3;
        cpa16(&Bh[r * 40 + c * 8], gBh + (size_t)r * ldb + k0 + c * 8);
        cpa16(&Bl[r * 40 + c * 8], gBl + (size_t)r * ldb + k0 + c * 8);
    }
}

__device__ __forceinline__ void mk_offsets(int wm, int wn, int lane,
                                           uint32_t* oA, uint32_t* oB) {
    #pragma unroll
    for (int mi = 0; mi < 2; mi++) {
        int row = wm * 32 + mi * 16 + (lane & 15);
        oA[mi] = (uint32_t)(row * ROWB + (8 * (lane >> 4)) * 2);
    }
    #pragma unroll
    for (int p = 0; p < 2; p++) {
        int row = wn * 32 + p * 16 + ((lane >> 4) << 3) + (lane & 7);
        oB[p] = (uint32_t)(A_BYTES + row * ROWB + (8 * ((lane >> 3) & 1)) * 2);
    }
}

__device__ __forceinline__ void compute_stage(uint32_t sb,
                                              const uint32_t* oA, const uint32_t* oB,
                                              float acc[2][4][4]) {
    #pragma unroll
    for (int kk = 0; kk < 2; kk++) {
        uint32_t af[2][4], bh[2][4], bl[2][4];
        ldm_x4(af[0], sb + oA[0] + kk * 32);
        ldm_x4(af[1], sb + oA[1] + kk * 32);
        ldm_x4(bh[0], sb + oB[0] + kk * 32);
        ldm_x4(bh[1], sb + oB[1] + kk * 32);
        ldm_x4(bl[0], sb + oB[0] + B_BYTES + kk * 32);
        ldm_x4(bl[1], sb + oB[1] + B_BYTES + kk * 32);
        #pragma unroll
        for (int mi = 0; mi < 2; mi++)
            #pragma unroll
            for (int p = 0; p < 2; p++) {
                mma16(acc[mi][2*p],     af[mi], &bh[p][0]);
                mma16(acc[mi][2*p + 1], af[mi], &bh[p][2]);
                mma16(acc[mi][2*p],     af[mi], &bl[p][0]);
                mma16(acc[mi][2*p + 1], af[mi], &bl[p][2]);
            }
    }
}

// 2-stage ring, 1 sync per stage. Safe because load(it+1) is issued AFTER the
// __syncthreads() that guarantees all warps finished compute(it-1), which is
// the last user of buffer (it+1)&1.
#define GEMM_RING(KT, GA, LDA_, GBH, GBL)                                        \
    load_stage(dynsm, GA, LDA_, GBH, GBL, LDA_, 0, t);  CPA_COMMIT;              \
    for (int it = 0; it < (KT); it++) {                                          \
        asm volatile("cp.async.wait_group 0;");                                  \
        __syncthreads();                                                         \
        if (it + 1 < (KT)) {                                                     \
            load_stage(dynsm + ((it + 1) & 1) * STG_B, GA, LDA_, GBH, GBL,       \
                       LDA_, (it + 1) * 32, t);                                  \
            CPA_COMMIT;                                                          \
        }                                                                        \
        compute_stage(sb0 + ((it) & 1) * STG_B, oA, oB, acc);                    \
    }

// ---------------- GEMM1 + fused chunk reduce ---------------------------------
// grid (16, 256): x = state-group (32 n's, 64 bcat rows), y = chunk (128 L-rows)
__global__ __launch_bounds__(256, 4) void k_gemm1() {
    extern __shared__ char dynsm[];
    __shared__ float2 seg[4][32];
    int t = threadIdx.x;
    int w = t >> 5, lane = t & 31, g = lane >> 2, t4 = lane & 3;
    int wm = w >> 1, wn = w & 1;
    int row0 = blockIdx.y * 128;
    int n0 = blockIdx.x * 32;
    uint32_t sb0 = smem_u32(dynsm);

    uint32_t oA[2], oB[2];
    mk_offsets(wm, wn, lane, oA, oB);

    const __half* gA  = g_uh   + (size_t)row0 * HH;
    const __half* gBh = g_bchi + (size_t)(blockIdx.x * 64) * HH;
    const __half* gBl = g_bclo + (size_t)(blockIdx.x * 64) * HH;

    float acc[2][4][4] = {};
    GEMM_RING(HH / 32, gA, HH, gBh, gBl);
    __syncthreads();

    float (*ep)[68] = (float(*)[68])dynsm;
    #pragma unroll
    for (int mi = 0; mi < 2; mi++) {
        int r0 = wm * 32 + mi * 16 + g;
        #pragma unroll
        for (int ni = 0; ni < 4; ni++) {
            int c = wn * 32 + ni * 8 + 2 * t4;
            *(float2*)&ep[r0][c]     = make_float2(acc[mi][ni][0], acc[mi][ni][1]);
            *(float2*)&ep[r0 + 8][c] = make_float2(acc[mi][ni][2], acc[mi][ni][3]);
        }
    }
    __syncthreads();

    // coalesced fp16 write of Bu
    #pragma unroll
    for (int i = 0; i < 16; i++) {
        int fi = t + i * 256;
        int r = fi >> 5, p = fi & 31;
        if (p < 16) {
            __half2 v = __halves2half2(__float2half_rn(ep[r][2*p]),
                                       __float2half_rn(ep[r][2*p + 1]));
            *(__half2*)&g_bur[(size_t)(row0 + r) * NS + n0 + 2*p] = v;
        } else {
            int q = p - 16;
            __half2 v = __halves2half2(__float2half_rn(ep[r][32 + 2*q]),
                                       __float2half_rn(ep[r][32 + 2*q + 1]));
            *(__half2*)&g_bui[(size_t)(row0 + r) * NS + n0 + 2*q] = v;
        }
    }

    // fused chunk Horner
    if (w < 4) {
        float2 lam = g_lam[n0 + lane];
        float2 b = make_float2(0.f, 0.f);
        int rbase = w * 32;
        #pragma unroll 4
        for (int r = 0; r < 32; r++) {
            float2 tt = cmul(lam, b);
            b = make_float2(tt.x + ep[rbase + r][lane],
                            tt.y + ep[rbase + r][32 + lane]);
        }
        seg[w][lane] = b;
    }
    __syncthreads();
    if (w == 0) {
        float2 lam = g_lam[n0 + lane];
        float2 l32 = lam;
        #pragma unroll
        for (int i = 0; i < 5; i++) l32 = cmul(l32, l32);
        float2 b = seg[0][lane];
        #pragma unroll
        for (int s = 1; s < 4; s++) {
            float2 tt = cmul(l32, b);
            b = make_float2(tt.x + seg[s][lane].x, tt.y + seg[s][lane].y);
        }
        g_chunk[blockIdx.y * NS + n0 + lane] = b;
    }
}

// ---------------- two-level cross-chunk scan ----------------------------------
__global__ __launch_bounds__(512) void k_scan1() {
    int s = blockIdx.x, n = threadIdx.x;
    float2 lamT = g_lamT[n];
    float2 v[16];
    #pragma unroll
    for (int j = 0; j < 16; j++) v[j] = g_chunk[(s * 16 + j) * NS + n];
    float2 b = make_float2(0.f, 0.f);
    #pragma unroll
    for (int j = 0; j < 16; j++) {
        float2 tt = cmul(lamT, b);
        b = make_float2(tt.x + v[j].x, tt.y + v[j].y);
    }
    g_seg[s * NS + n] = b;
}

__global__ __launch_bounds__(512) void k_scan2() {
    int n = threadIdx.x;
    float2 lamT = g_lamT[n];
    float2 l16 = lamT;
    #pragma unroll
    for (int i = 0; i < 4; i++) l16 = cmul(l16, l16);
    float2 v[16];
    #pragma unroll
    for (int s = 0; s < 16; s++) v[s] = g_seg[s * NS + n];
    float2 p = make_float2(0.f, 0.f);
    #pragma unroll
    for (int s = 0; s < 16; s++) {
        g_segpref[s * NS + n] = p;
        float2 tt = cmul(l16, p);
        p = make_float2(tt.x + v[s].x, tt.y + v[s].y);
    }
}

// ---------------- apply: segpref + intra-segment walk, batch-8 MLP ------------
__global__ __launch_bounds__(512) void k_apply() {
    int c = blockIdx.x;
    int n = threadIdx.x;
    int s = c >> 4, jrem = c & 15;
    float2 lam  = g_lam[n];
    float2 lamT = g_lamT[n];

    float2 carry = g_segpref[s * NS + n];
    for (int j = 0; j < jrem; j++) {
        float2 b = g_chunk[(s * 16 + j) * NS + n];
        float2 tt = cmul(lamT, carry);
        carry = make_float2(tt.x + b.x, tt.y + b.y);
    }

    size_t base = (size_t)c * CT * NS + n;
    for (int j0 = 0; j0 < CT; j0 += 8) {
        float vr[8], vi[8];
        #pragma unroll
        for (int k = 0; k < 8; k++) {
            size_t idx = base + (size_t)(j0 + k) * NS;
            vr[k] = __half2float(g_bur[idx]);
            vi[k] = __half2float(g_bui[idx]);
        }
        #pragma unroll
        for (int k = 0; k < 8; k++) {
            float2 tt = cmul(lam, carry);
            carry = make_float2(tt.x + vr[k], tt.y + vi[k]);
            size_t l = (size_t)c * CT + j0 + k;
            g_sh[l * (2*NS) + n]      = __float2half_rn(carry.x);
            g_sh[l * (2*NS) + NS + n] = __float2half_rn(carry.y);
        }
    }
}

// ---------------- GEMM2: Y = S @ cc^T + D*U ----------------------------------
// grid (4, 256): x = h-tile(64), y = L-tile(128). K = 1024.
__global__ __launch_bounds__(256, 4) void k_gemm2(const float* __restrict__ U,
                                                  const float* __restrict__ Dg,
                                                  float* __restrict__ Y) {
    extern __shared__ char dynsm[];
    int t = threadIdx.x;
    int w = t >> 5, lane = t & 31, g = lane >> 2, t4 = lane & 3;
    int wm = w >> 1, wn = w & 1;
    int row0 = blockIdx.y * 128;
    int col0 = blockIdx.x * 64;
    uint32_t sb0 = smem_u32(dynsm);

    uint32_t oA[2], oB[2];
    mk_offsets(wm, wn, lane, oA, oB);

    const int LDA = 2 * NS;
    const __half* gA  = g_sh   + (size_t)row0 * LDA;
    const __half* gBh = g_cchi + (size_t)col0 * LDA;
    const __half* gBl = g_cclo + (size_t)col0 * LDA;

    float acc[2][4][4] = {};
    GEMM_RING((2 * NS) / 32, gA, LDA, gBh, gBl);

    #pragma unroll
    for (int mi = 0; mi < 2; mi++) {
        int l0 = row0 + wm * 32 + mi * 16 + g;
        #pragma unroll
        for (int ni = 0; ni < 4; ni++) {
            int h = col0 + wn * 32 + ni * 8 + 2 * t4;
            float2 d2 = *(const float2*)&Dg[h];
            float2 u0 = *(const float2*)&U[(size_t)l0 * HH + h];
            float2 u1 = *(const float2*)&U[(size_t)(l0 + 8) * HH + h];
            *(float2*)&Y[(size_t)l0 * HH + h] =
                make_float2(acc[mi][ni][0] + d2.x * u0.x, acc[mi][ni][1] + d2.y * u0.y);
            *(float2*)&Y[(size_t)(l0 + 8) * HH + h] =
                make_float2(acc[mi][ni][2] + d2.x * u1.x, acc[mi][ni][3] + d2.y * u1.y);
        }
    }
}

// ---------------- launch ----------------------------------------------------
extern "C" void kernel_launch(void* const* d_in, const int* in_sizes, int n_in,
                              void* d_out, int out_size) {
    const float* U        = (const float*)d_in[0];
    const float* nu_log   = (const float*)d_in[1];
    const float* theta_lg = (const float*)d_in[2];
    const float* Bre      = (const float*)d_in[3];
    const float* Bim      = (const float*)d_in[4];
    const float* Cre      = (const float*)d_in[5];
    const float* Cim      = (const float*)d_in[6];
    const float* D        = (const float*)d_in[7];
    float* Y = (float*)d_out;

    cudaFuncSetAttribute(k_gemm1, cudaFuncAttributeMaxDynamicSharedMemorySize, SMEM_DYN);
    cudaFuncSetAttribute(k_gemm2, cudaFuncAttributeMaxDynamicSharedMemorySize, SMEM_DYN);

    // order keeps k_gemm1 at launch slot 4 (where ncu lands)
    k_setup<<<1, 512>>>(nu_log, theta_lg);
    k_cvtU<<<(LL * HH / 4 + 255) / 256, 256>>>(U);
    k_bn<<<(NS * HH + 255) / 256, 256>>>(Bre, Bim);
    k_gemm1<<<dim3(16, 256), 256, SMEM_DYN>>>();
    k_cc<<<(HH * NS + 255) / 256, 256>>>(Cre, Cim);
    k_scan1<<<16, 512>>>();
    k_scan2<<<1, 512>>>();
    k_apply<<<NC, 512>>>();
    k_gemm2<<<dim3(4, 256), 256, SMEM_DYN>>>(U, D, Y);
}

// round 13
// speedup vs baseline: 1.6729x; 1.1713x over previous
#include <cuda_runtime.h>
#include <cuda_fp16.h>
#include <cstdint>

#define LL 32768
#define HH 256
#define NS 512
#define CT 128
#define NC 256

// ---------------- device scratch ---------------------------------------------
__device__ __half g_bur[(size_t)LL * NS];      // Bu real fp16
__device__ __half g_bui[(size_t)LL * NS];      // Bu imag fp16
__device__ __half g_sh[(size_t)LL * 2 * NS];   // states fp16 [L][1024] (re|im)
__device__ __half g_uh[(size_t)LL * HH];       // U fp16
__device__ __half g_bc[2 * NS * HH];           // reordered gamma-B fp16 (single)
__device__ __half g_cchi[HH * 2 * NS];         // [256][1024]: Cre | -Cim hi
__device__ __half g_cclo[HH * 2 * NS];
__device__ float2 g_chunk[NC * NS];
__device__ float2 g_seg[16 * NS];
__device__ float2 g_segpref[16 * NS];
__device__ float2 g_lam[NS];
__device__ float2 g_lamT[NS];
__device__ float  g_gamma[NS];

// ---------------- helpers ----------------------------------------------------
__device__ __forceinline__ float2 cmul(float2 a, float2 b) {
    return make_float2(a.x * b.x - a.y * b.y, a.x * b.y + a.y * b.x);
}
__device__ __forceinline__ void h16_split(float x, __half& hi, __half& lo) {
    hi = __float2half_rn(x);
    lo = __float2half_rn(x - __half2float(hi));
}
__device__ __forceinline__ uint32_t smem_u32(const void* p) {
    return (uint32_t)__cvta_generic_to_shared(p);
}
__device__ __forceinline__ void cpa16(const void* dst_smem, const void* src) {
    asm volatile("cp.async.cg.shared.global [%0], [%1], 16;"
                 :: "r"(smem_u32(dst_smem)), "l"(src));
}
#define CPA_COMMIT asm volatile("cp.async.commit_group;")

__device__ __forceinline__ void mma16(float* c, const uint32_t* a, const uint32_t* b) {
    asm volatile(
        "mma.sync.aligned.m16n8k16.row.col.f32.f16.f16.f32 "
        "{%0,%1,%2,%3},{%4,%5,%6,%7},{%8,%9},{%0,%1,%2,%3};"
        : "+f"(c[0]), "+f"(c[1]), "+f"(c[2]), "+f"(c[3])
        : "r"(a[0]), "r"(a[1]), "r"(a[2]), "r"(a[3]), "r"(b[0]), "r"(b[1]));
}
__device__ __forceinline__ void ldm_x4(uint32_t* r, uint32_t addr) {
    asm volatile("ldmatrix.sync.aligned.m8n8.x4.shared.b16 {%0,%1,%2,%3}, [%4];"
                 : "=r"(r[0]), "=r"(r[1]), "=r"(r[2]), "=r"(r[3]) : "r"(addr));
}

// ---------------- setup kernels ----------------------------------------------
__global__ void k_setup(const float* __restrict__ nu_log,
                        const float* __restrict__ theta_log) {
    int n = threadIdx.x;
    if (n >= NS) return;
    float nu    = expf(nu_log[n]);
    float theta = expf(theta_log[n]);
    float mag   = expf(-nu);
    float2 lam  = make_float2(mag * cosf(theta), mag * sinf(theta));
    g_lam[n]   = lam;
    g_gamma[n] = sqrtf(fmaxf(1.0f - mag * mag, 0.0f));
    float2 t = lam;
    #pragma unroll
    for (int i = 0; i < 7; i++) t = cmul(t, t);
    g_lamT[n] = t;
}

// fused prep: U->fp16 (blocks [0,8192)), gamma-B (blocks [8192,8704)),
// C concat (blocks [8704,9216)). Runs after k_setup (needs g_gamma).
__global__ void k_prep(const float* __restrict__ U,
                       const float* __restrict__ Bre, const float* __restrict__ Bim,
                       const float* __restrict__ Cre, const float* __restrict__ Cim) {
    int b = blockIdx.x;
    if (b < 8192) {
        size_t i = ((size_t)b * 256 + threadIdx.x) * 4;
        float4 v = *(const float4*)&U[i];
        *(__half2*)&g_uh[i]     = __halves2half2(__float2half_rn(v.x), __float2half_rn(v.y));
        *(__half2*)&g_uh[i + 2] = __halves2half2(__float2half_rn(v.z), __float2half_rn(v.w));
    } else if (b < 8704) {
        int i = (b - 8192) * 256 + threadIdx.x;   // < NS*HH
        int n = i / HH, h = i % HH;
        float gam = g_gamma[n];
        int grp = n >> 5, j = n & 31;
        g_bc[(size_t)(grp * 64 + j) * HH + h]      = __float2half_rn(Bre[i] * gam);
        g_bc[(size_t)(grp * 64 + 32 + j) * HH + h] = __float2half_rn(Bim[i] * gam);
    } else {
        int i = (b - 8704) * 256 + threadIdx.x;   // < HH*NS
        int h = i / NS, n = i % NS;
        __half hi, lo;
        h16_split(Cre[i], hi, lo);
        g_cchi[(size_t)h * (2*NS) + n] = hi;  g_cclo[(size_t)h * (2*NS) + n] = lo;
        h16_split(-Cim[i], hi, lo);
        g_cchi[(size_t)h * (2*NS) + NS + n] = hi;  g_cclo[(size_t)h * (2*NS) + NS + n] = lo;
    }
}

// ---------------- GEMM machinery ---------------------------------------------
// Block 128(M) x 64(N) x 32(K); 256 thr = 8 warps (4M x 2N); warp 32x32.
// gemm1: B single pass. gemm2: B hi+lo 2-pass. 2-stage ring, 1 sync/stage.
static constexpr int ROWB    = 80;
static constexpr int A_BYTES = 128 * ROWB;             // 10240
static constexpr int B_BYTES = 64 * ROWB;              // 5120
static constexpr int STG1    = A_BYTES + B_BYTES;      // 15360
static constexpr int STG2    = A_BYTES + 2 * B_BYTES;  // 20480
static constexpr int SMEM1   = 128 * 68 * 4;           // 34816 (>= 2*STG1, epilogue tile)
static constexpr int SMEM2   = 2 * STG2;               // 40960

template<bool LO>
__device__ __forceinline__ void load_stage(char* stg, const __half* gA, int lda,
                                           const __half* gBh, const __half* gBl,
                                           int ldb, int k0, int t) {
    __half* A  = (__half*)stg;
    __half* Bh = (__half*)(stg + A_BYTES);
    __half* Bl = (__half*)(stg + A_BYTES + B_BYTES);
    #pragma unroll
    for (int i = 0; i < 2; i++) {
        int idx = t + i * 256;
        int r = idx >> 2, c = idx & 3;
        cpa16(&A[r * 40 + c * 8], gA + (size_t)r * lda + k0 + c * 8);
    }
    {
        int r = t >> 2, c = t & 3;
        cpa16(&Bh[r * 40 + c * 8], gBh + (size_t)r * ldb + k0 + c * 8);
        if (LO) cpa16(&Bl[r * 40 + c * 8], gBl + (size_t)r * ldb + k0 + c * 8);
    }
}

__device__ __forceinline__ void mk_offsets(int wm, int wn, int lane,
                                           uint32_t* oA, uint32_t* oB) {
    #pragma unroll
    for (int mi = 0; mi < 2; mi++) {
        int row = wm * 32 + mi * 16 + (lane & 15);
        oA[mi] = (uint32_t)(row * ROWB + (8 * (lane >> 4)) * 2);
    }
    #pragma unroll
    for (int p = 0; p < 2; p++) {
        int row = wn * 32 + p * 16 + ((lane >> 4) << 3) + (lane & 7);
        oB[p] = (uint32_t)(A_BYTES + row * ROWB + (8 * ((lane >> 3) & 1)) * 2);
    }
}

template<bool LO>
__device__ __forceinline__ void compute_stage(uint32_t sb,
                                              const uint32_t* oA, const uint32_t* oB,
                                              float acc[2][4][4]) {
    #pragma unroll
    for (int kk = 0; kk < 2; kk++) {
        uint32_t af[2][4], bh[2][4], bl[2][4];
        ldm_x4(af[0], sb + oA[0] + kk * 32);
        ldm_x4(af[1], sb + oA[1] + kk * 32);
        ldm_x4(bh[0], sb + oB[0] + kk * 32);
        ldm_x4(bh[1], sb + oB[1] + kk * 32);
        if (LO) {
            ldm_x4(bl[0], sb + oB[0] + B_BYTES + kk * 32);
            ldm_x4(bl[1], sb + oB[1] + B_BYTES + kk * 32);
        }
        #pragma unroll
        for (int mi = 0; mi < 2; mi++)
            #pragma unroll
            for (int p = 0; p < 2; p++) {
                mma16(acc[mi][2*p],     af[mi], &bh[p][0]);
                mma16(acc[mi][2*p + 1], af[mi], &bh[p][2]);
                if (LO) {
                    mma16(acc[mi][2*p],     af[mi], &bl[p][0]);
                    mma16(acc[mi][2*p + 1], af[mi], &bl[p][2]);
                }
            }
    }
}

// 2-stage ring, 1 sync per stage; load(it+1) issued after the sync that retires
// compute(it-1), the last user of buffer (it+1)&1.
#define GEMM_RING(KT, GA, LDA_, GBH, GBL, STG, LO)                               \
    load_stage<LO>(dynsm, GA, LDA_, GBH, GBL, LDA_, 0, t);  CPA_COMMIT;          \
    for (int it = 0; it < (KT); it++) {                                          \
        asm volatile("cp.async.wait_group 0;");                                  \
        __syncthreads();                                                         \
        if (it + 1 < (KT)) {                                                     \
            load_stage<LO>(dynsm + ((it + 1) & 1) * (STG), GA, LDA_, GBH, GBL,   \
                           LDA_, (it + 1) * 32, t);                              \
            CPA_COMMIT;                                                          \
        }                                                                        \
        compute_stage<LO>(sb0 + ((it) & 1) * (STG), oA, oB, acc);                \
    }

// ---------------- GEMM1 + fused chunk reduce ---------------------------------
// grid (16, 256): x = state-group (32 n's, 64 bcat rows), y = chunk (128 L-rows)
__global__ __launch_bounds__(256, 4) void k_gemm1() {
    extern __shared__ char dynsm[];
    __shared__ float2 seg[4][32];
    int t = threadIdx.x;
    int w = t >> 5, lane = t & 31, g = lane >> 2, t4 = lane & 3;
    int wm = w >> 1, wn = w & 1;
    int row0 = blockIdx.y * 128;
    int n0 = blockIdx.x * 32;
    uint32_t sb0 = smem_u32(dynsm);

    uint32_t oA[2], oB[2];
    mk_offsets(wm, wn, lane, oA, oB);

    const __half* gA = g_uh + (size_t)row0 * HH;
    const __half* gB = g_bc + (size_t)(blockIdx.x * 64) * HH;

    float acc[2][4][4] = {};
    GEMM_RING(HH / 32, gA, HH, gB, (const __half*)nullptr, STG1, false);
    __syncthreads();

    float (*ep)[68] = (float(*)[68])dynsm;
    #pragma unroll
    for (int mi = 0; mi < 2; mi++) {
        int r0 = wm * 32 + mi * 16 + g;
        #pragma unroll
        for (int ni = 0; ni < 4; ni++) {
            int c = wn * 32 + ni * 8 + 2 * t4;
            *(float2*)&ep[r0][c]     = make_float2(acc[mi][ni][0], acc[mi][ni][1]);
            *(float2*)&ep[r0 + 8][c] = make_float2(acc[mi][ni][2], acc[mi][ni][3]);
        }
    }
    __syncthreads();

    // coalesced fp16 write of Bu
    #pragma unroll
    for (int i = 0; i < 16; i++) {
        int fi = t + i * 256;
        int r = fi >> 5, p = fi & 31;
        if (p < 16) {
            __half2 v = __halves2half2(__float2half_rn(ep[r][2*p]),
                                       __float2half_rn(ep[r][2*p + 1]));
            *(__half2*)&g_bur[(size_t)(row0 + r) * NS + n0 + 2*p] = v;
        } else {
            int q = p - 16;
            __half2 v = __halves2half2(__float2half_rn(ep[r][32 + 2*q]),
                                       __float2half_rn(ep[r][32 + 2*q + 1]));
            *(__half2*)&g_bui[(size_t)(row0 + r) * NS + n0 + 2*q] = v;
        }
    }

    // fused chunk Horner
    if (w < 4) {
        float2 lam = g_lam[n0 + lane];
        float2 b = make_float2(0.f, 0.f);
        int rbase = w * 32;
        #pragma unroll 4
        for (int r = 0; r < 32; r++) {
            float2 tt = cmul(lam, b);
            b = make_float2(tt.x + ep[rbase + r][lane],
                            tt.y + ep[rbase + r][32 + lane]);
        }
        seg[w][lane] = b;
    }
    __syncthreads();
    if (w == 0) {
        float2 lam = g_lam[n0 + lane];
        float2 l32 = lam;
        #pragma unroll
        for (int i = 0; i < 5; i++) l32 = cmul(l32, l32);
        float2 b = seg[0][lane];
        #pragma unroll
        for (int s = 1; s < 4; s++) {
            float2 tt = cmul(l32, b);
            b = make_float2(tt.x + seg[s][lane].x, tt.y + seg[s][lane].y);
        }
        g_chunk[blockIdx.y * NS + n0 + lane] = b;
    }
}

// ---------------- two-level cross-chunk scan ----------------------------------
__global__ __launch_bounds__(512) void k_scan1() {
    int s = blockIdx.x, n = threadIdx.x;
    float2 lamT = g_lamT[n];
    float2 v[16];
    #pragma unroll
    for (int j = 0; j < 16; j++) v[j] = g_chunk[(s * 16 + j) * NS + n];
    float2 b = make_float2(0.f, 0.f);
    #pragma unroll
    for (int j = 0; j < 16; j++) {
        float2 tt = cmul(lamT, b);
        b = make_float2(tt.x + v[j].x, tt.y + v[j].y);
    }
    g_seg[s * NS + n] = b;
}

__global__ __launch_bounds__(512) void k_scan2() {
    int n = threadIdx.x;
    float2 lamT = g_lamT[n];
    float2 l16 = lamT;
    #pragma unroll
    for (int i = 0; i < 4; i++) l16 = cmul(l16, l16);
    float2 v[16];
    #pragma unroll
    for (int s = 0; s < 16; s++) v[s] = g_seg[s * NS + n];
    float2 p = make_float2(0.f, 0.f);
    #pragma unroll
    for (int s = 0; s < 16; s++) {
        g_segpref[s * NS + n] = p;
        float2 tt = cmul(l16, p);
        p = make_float2(tt.x + v[s].x, tt.y + v[s].y);
    }
}

// ---------------- apply: segpref + intra-segment walk, batch-8 MLP ------------
__global__ __launch_bounds__(512) void k_apply() {
    int c = blockIdx.x;
    int n = threadIdx.x;
    int s = c >> 4, jrem = c & 15;
    float2 lam  = g_lam[n];
    float2 lamT = g_lamT[n];

    float2 carry = g_segpref[s * NS + n];
    for (int j = 0; j < jrem; j++) {
        float2 b = g_chunk[(s * 16 + j) * NS + n];
        float2 tt = cmul(lamT, carry);
        carry = make_float2(tt.x + b.x, tt.y + b.y);
    }

    size_t base = (size_t)c * CT * NS + n;
    for (int j0 = 0; j0 < CT; j0 += 8) {
        float vr[8], vi[8];
        #pragma unroll
        for (int k = 0; k < 8; k++) {
            size_t idx = base + (size_t)(j0 + k) * NS;
            vr[k] = __half2float(g_bur[idx]);
            vi[k] = __half2float(g_bui[idx]);
        }
        #pragma unroll
        for (int k = 0; k < 8; k++) {
            float2 tt = cmul(lam, carry);
            carry = make_float2(tt.x + vr[k], tt.y + vi[k]);
            size_t l = (size_t)c * CT + j0 + k;
            g_sh[l * (2*NS) + n]      = __float2half_rn(carry.x);
            g_sh[l * (2*NS) + NS + n] = __float2half_rn(carry.y);
        }
    }
}

// ---------------- GEMM2: Y = S @ cc^T + D*U (C hi+lo 2-pass) ------------------
// grid (4, 256): x = h-tile(64), y = L-tile(128). K = 1024.
__global__ __launch_bounds__(256, 4) void k_gemm2(const float* __restrict__ U,
                                                  const float* __restrict__ Dg,
                                                  float* __restrict__ Y) {
    extern __shared__ char dynsm[];
    int t = threadIdx.x;
    int w = t >> 5, lane = t & 31, g = lane >> 2, t4 = lane & 3;
    int wm = w >> 1, wn = w & 1;
    int row0 = blockIdx.y * 128;
    int col0 = blockIdx.x * 64;
    uint32_t sb0 = smem_u32(dynsm);

    uint32_t oA[2], oB[2];
    mk_offsets(wm, wn, lane, oA, oB);

    const int LDA = 2 * NS;
    const __half* gA  = g_sh   + (size_t)row0 * LDA;
    const __half* gBh = g_cchi + (size_t)col0 * LDA;
    const __half* gBl = g_cclo + (size_t)col0 * LDA;

    float acc[2][4][4] = {};
    GEMM_RING((2 * NS) / 32, gA, LDA, gBh, gBl, STG2, true);

    #pragma unroll
    for (int mi = 0; mi < 2; mi++) {
        int l0 = row0 + wm * 32 + mi * 16 + g;
        #pragma unroll
        for (int ni = 0; ni < 4; ni++) {
            int h = col0 + wn * 32 + ni * 8 + 2 * t4;
            float2 d2 = *(const float2*)&Dg[h];
            float2 u0 = *(const float2*)&U[(size_t)l0 * HH + h];
            float2 u1 = *(const float2*)&U[(size_t)(l0 + 8) * HH + h];
            *(float2*)&Y[(size_t)l0 * HH + h] =
                make_float2(acc[mi][ni][0] + d2.x * u0.x, acc[mi][ni][1] + d2.y * u0.y);
            *(float2*)&Y[(size_t)(l0 + 8) * HH + h] =
                make_float2(acc[mi][ni][2] + d2.x * u1.x, acc[mi][ni][3] + d2.y * u1.y);
        }
    }
}

// ---------------- launch ----------------------------------------------------
extern "C" void kernel_launch(void* const* d_in, const int* in_sizes, int n_in,
                              void* d_out, int out_size) {
    const float* U        = (const float*)d_in[0];
    const float* nu_log   = (const float*)d_in[1];
    const float* theta_lg = (const float*)d_in[2];
    const float* Bre      = (const float*)d_in[3];
    const float* Bim      = (const float*)d_in[4];
    const float* Cre      = (const float*)d_in[5];
    const float* Cim      = (const float*)d_in[6];
    const float* D        = (const float*)d_in[7];
    float* Y = (float*)d_out;

    cudaFuncSetAttribute(k_gemm1, cudaFuncAttributeMaxDynamicSharedMemorySize, SMEM1);
    cudaFuncSetAttribute(k_gemm2, cudaFuncAttributeMaxDynamicSharedMemorySize, SMEM2);

    k_setup<<<1, 512>>>(nu_log, theta_lg);
    k_prep<<<9216, 256>>>(U, Bre, Bim, Cre, Cim);
    k_gemm1<<<dim3(16, 256), 256, SMEM1>>>();
    k_scan1<<<16, 512>>>();
    k_scan2<<<1, 512>>>();
    k_apply<<<NC, 512>>>();
    k_gemm2<<<dim3(4, 256), 256, SMEM2>>>(U, D, Y);
}